// round 2
// baseline (speedup 1.0000x reference)
#include <cuda_runtime.h>
#include <cstdint>

// Problem constants
#define TT 512
#define BB 32
#define EE 256
#define HH 512
// seq buffer: [dir][t*32+b][512]
#define SEQ_ELEMS (2*TT*BB*HH)   // 16777216
#define DIR_STRIDE (TT*BB*HH)    // 8388608

// Scratch (static device memory; no allocations allowed)
__device__ float g_pre[SEQ_ELEMS];   // pre-activations, reused for both layers
__device__ float g_seq[SEQ_ELEMS];   // layer-0 hidden sequence (input to layer-1 GEMM)
__device__ float g_hbuf[2][2][BB*HH]; // [dir][double-buffer][b*512+k]
__device__ int   g_cnt[2][2];        // [layer][dir] step completion counters

__global__ void zero_counters() {
    if (threadIdx.x < 4) ((int*)g_cnt)[threadIdx.x] = 0;
}

// ---------------------------------------------------------------------------
// SGEMM-NT: out[m][n] = sum_k A[m][k] * W[n][k] + bias(n)
// M=16384, N=1024 (dirs stacked), K in {256,1024}
// MODE 0: A = xs [B,T,E] accessed as m=(t*32+b) -> xs[b][t][k]
// MODE 1: A = g_seq, k -> (dir=k>>9, j=k&511)
// out written as pre[dir][m][j]
// ---------------------------------------------------------------------------
template<int MODE>
__global__ __launch_bounds__(256) void gemm_kernel(
    const float* __restrict__ A, const float* __restrict__ W,
    const float* __restrict__ bias, float* __restrict__ out, int K)
{
    __shared__ float As[8][128];
    __shared__ float Bs[8][128];
    const int tid = threadIdx.x;
    const int m0 = blockIdx.y * 128;
    const int n0 = blockIdx.x * 128;
    const int lrow = tid >> 1;
    const int lk4  = (tid & 1) * 4;
    const int tx = tid & 15, ty = tid >> 4;

    float acc[8][8];
    #pragma unroll
    for (int i = 0; i < 8; i++)
        #pragma unroll
        for (int j = 0; j < 8; j++) acc[i][j] = 0.0f;

    for (int k0 = 0; k0 < K; k0 += 8) {
        const int ka = k0 + lk4;
        const int m  = m0 + lrow;
        float4 av;
        if (MODE == 0) {
            av = *(const float4*)(A + (size_t)(m & 31) * (TT*EE) + (size_t)(m >> 5) * EE + ka);
        } else {
            av = *(const float4*)(A + (size_t)(ka >> 9) * DIR_STRIDE + (size_t)m * 512 + (ka & 511));
        }
        float4 bv = *(const float4*)(W + (size_t)(n0 + lrow) * K + ka);
        As[lk4+0][lrow] = av.x; As[lk4+1][lrow] = av.y;
        As[lk4+2][lrow] = av.z; As[lk4+3][lrow] = av.w;
        Bs[lk4+0][lrow] = bv.x; Bs[lk4+1][lrow] = bv.y;
        Bs[lk4+2][lrow] = bv.z; Bs[lk4+3][lrow] = bv.w;
        __syncthreads();

        #pragma unroll
        for (int kk = 0; kk < 8; kk++) {
            float a[8], b[8];
            #pragma unroll
            for (int i = 0; i < 8; i++) a[i] = As[kk][ty*8 + i];
            #pragma unroll
            for (int j = 0; j < 8; j++) b[j] = Bs[kk][tx*8 + j];
            #pragma unroll
            for (int i = 0; i < 8; i++)
                #pragma unroll
                for (int j = 0; j < 8; j++)
                    acc[i][j] += a[i] * b[j];
        }
        __syncthreads();
    }

    #pragma unroll
    for (int j = 0; j < 8; j++) {
        const int n   = n0 + tx*8 + j;
        const int dir = n >> 9;
        const int jj  = n & 511;
        const float bsum = bias[dir*1024 + jj] + bias[dir*1024 + 512 + jj];
        #pragma unroll
        for (int i = 0; i < 8; i++) {
            const int m = m0 + ty*8 + i;
            out[(size_t)dir * DIR_STRIDE + (size_t)m * 512 + jj] = acc[i][j] + bsum;
        }
    }
}

// ---------------------------------------------------------------------------
// Persistent recurrence kernel: 128 CTAs (64 per direction), 128 threads.
// Each CTA owns 8 output columns (j0..j0+7) of h; W_hh slice lives in smem.
// Per-step spin sync on g_cnt[LAYER][dir]; h double-buffered in global.
// LAYER 0: writes g_seq (layout == pre layout).
// LAYER 1: writes hs output [b][tau][dir*512+j].
// Both write hy rows (LAYER*2 + dir) on the final step.
// ---------------------------------------------------------------------------
template<int LAYER>
__global__ __launch_bounds__(128) void rec_kernel(
    const float* __restrict__ pre, const float* __restrict__ Whh,
    float* __restrict__ outA, float* __restrict__ hy)
{
    __shared__ float Wsh[8][512];
    const int dir = blockIdx.x >> 6;
    const int j0  = (blockIdx.x & 63) * 8;
    const int tid = threadIdx.x;
    const int w   = tid >> 5;
    const int b   = tid & 31;
    const int ja  = 2*w, jb = 2*w + 1;   // local j within chunk

    // Load W_hh rows [j0, j0+8) for this direction into smem
    const float* Wbase = Whh + (size_t)dir * (HH*HH) + (size_t)j0 * HH;
    for (int i = tid; i < 8 * 128; i += 128) {
        const int r = i >> 7;
        const int c = (i & 127) * 4;
        *(float4*)&Wsh[r][c] = *(const float4*)(Wbase + r * 512 + c);
    }
    __syncthreads();

    volatile int* cnt = &g_cnt[LAYER][dir];

    for (int t = 0; t < TT; t++) {
        const int tau = dir ? (TT - 1 - t) : t;
        const size_t pidx = (size_t)dir * DIR_STRIDE + (size_t)(tau*32 + b) * 512 + j0;
        float acc0 = pre[pidx + ja];
        float acc1 = pre[pidx + jb];

        if (t > 0) {
            if (tid == 0) {
                const int target = 64 * t;
                while (*cnt < target) { }
            }
            __syncthreads();
            __threadfence();
            const float4* hp = (const float4*)&g_hbuf[dir][(t-1) & 1][b * 512];
            #pragma unroll 8
            for (int k4 = 0; k4 < 128; k4++) {
                const float4 h4 = __ldcg(hp + k4);
                const float4 wa = *(const float4*)&Wsh[ja][k4 * 4];
                const float4 wb = *(const float4*)&Wsh[jb][k4 * 4];
                acc0 += h4.x*wa.x + h4.y*wa.y + h4.z*wa.z + h4.w*wa.w;
                acc1 += h4.x*wb.x + h4.y*wb.y + h4.z*wb.z + h4.w*wb.w;
            }
        }

        const float v0 = tanhf(acc0);
        const float v1 = tanhf(acc1);

        float* hb = &g_hbuf[dir][t & 1][b * 512 + j0];
        hb[ja] = v0; hb[jb] = v1;

        if (LAYER == 0) {
            float* o = outA + pidx;            // same layout as pre
            o[ja] = v0; o[jb] = v1;
        } else {
            float* o = outA + (size_t)b * (TT*2*HH) + (size_t)tau * (2*HH) + dir * 512 + j0;
            o[ja] = v0; o[jb] = v1;
        }
        if (t == TT - 1) {
            float* o = hy + (size_t)(LAYER*2 + dir) * (BB*HH) + b * 512 + j0;
            o[ja] = v0; o[jb] = v1;
        }

        __threadfence();
        __syncthreads();
        if (tid == 0) atomicAdd(&g_cnt[LAYER][dir], 1);
    }
}

extern "C" void kernel_launch(void* const* d_in, const int* in_sizes, int n_in,
                              void* d_out, int out_size)
{
    const float* xs    = (const float*)d_in[0];
    const float* w_ih0 = (const float*)d_in[1];
    const float* w_hh0 = (const float*)d_in[2];
    const float* b0    = (const float*)d_in[3];
    const float* w_ih1 = (const float*)d_in[4];
    const float* w_hh1 = (const float*)d_in[5];
    const float* b1    = (const float*)d_in[6];

    float* out_hs = (float*)d_out;                       // [B][T][2H]
    float* out_hy = (float*)d_out + (size_t)BB*TT*2*HH;  // [4][B][H]

    float* pre; cudaGetSymbolAddress((void**)&pre, g_pre);
    float* seq; cudaGetSymbolAddress((void**)&seq, g_seq);

    zero_counters<<<1, 32>>>();

    // Layer 0 input projection: K=256
    gemm_kernel<0><<<dim3(8, 128), 256>>>(xs, w_ih0, b0, pre, EE);
    // Layer 0 recurrence (both directions concurrently)
    rec_kernel<0><<<128, 128>>>(pre, w_hh0, seq, out_hy);
    // Layer 1 input projection: K=1024 over concatenated directions
    gemm_kernel<1><<<dim3(8, 128), 256>>>(seq, w_ih1, b1, pre, 2*HH);
    // Layer 1 recurrence, writes final hs + hy
    rec_kernel<1><<<128, 128>>>(pre, w_hh1, out_hs, out_hy);
}

// round 3
// speedup vs baseline: 2.3210x; 2.3210x over previous
#include <cuda_runtime.h>
#include <cstdint>

// Problem constants
#define TT 512
#define BB 32
#define EE 256
#define HH 512
#define SEQ_ELEMS (2*TT*BB*HH)   // 16777216
#define DIR_STRIDE (TT*BB*HH)    // 8388608

// Scratch (static device memory; no allocations allowed)
__device__ float g_pre[SEQ_ELEMS];            // pre-activations, reused for both layers
__device__ float g_seq[SEQ_ELEMS];            // layer-0 hidden sequence
__device__ float g_hbuf[2][2][BB*HH];         // [dir][double-buffer][b*512+k]
__device__ __align__(128) int g_cnt[2][2][32];   // arrival counters, 1 line each
__device__ __align__(128) int g_flag[2][2][32];  // epoch flags, 1 line each

__global__ void zero_counters() {
    int i = threadIdx.x;
    if (i < 128) { ((int*)g_cnt)[i] = 0; ((int*)g_flag)[i] = 0; }
}

// ---- scoped memory-model helpers -----------------------------------------
__device__ __forceinline__ int ld_acquire_gpu(const int* p) {
    int v;
    asm volatile("ld.acquire.gpu.global.s32 %0, [%1];" : "=r"(v) : "l"(p));
    return v;
}
__device__ __forceinline__ int atom_add_release_gpu(int* p, int v) {
    int o;
    asm volatile("atom.release.gpu.global.add.s32 %0, [%1], %2;"
                 : "=r"(o) : "l"(p), "r"(v));
    return o;
}
__device__ __forceinline__ void st_release_gpu(int* p, int v) {
    asm volatile("st.release.gpu.global.s32 [%0], %1;" :: "l"(p), "r"(v));
}

// ---------------------------------------------------------------------------
// SGEMM-NT: out[m][n] = sum_k A[m][k] * W[n][k] + bias(n)   (unchanged)
// ---------------------------------------------------------------------------
template<int MODE>
__global__ __launch_bounds__(256) void gemm_kernel(
    const float* __restrict__ A, const float* __restrict__ W,
    const float* __restrict__ bias, float* __restrict__ out, int K)
{
    __shared__ float As[8][128];
    __shared__ float Bs[8][128];
    const int tid = threadIdx.x;
    const int m0 = blockIdx.y * 128;
    const int n0 = blockIdx.x * 128;
    const int lrow = tid >> 1;
    const int lk4  = (tid & 1) * 4;
    const int tx = tid & 15, ty = tid >> 4;

    float acc[8][8];
    #pragma unroll
    for (int i = 0; i < 8; i++)
        #pragma unroll
        for (int j = 0; j < 8; j++) acc[i][j] = 0.0f;

    for (int k0 = 0; k0 < K; k0 += 8) {
        const int ka = k0 + lk4;
        const int m  = m0 + lrow;
        float4 av;
        if (MODE == 0) {
            av = *(const float4*)(A + (size_t)(m & 31) * (TT*EE) + (size_t)(m >> 5) * EE + ka);
        } else {
            av = *(const float4*)(A + (size_t)(ka >> 9) * DIR_STRIDE + (size_t)m * 512 + (ka & 511));
        }
        float4 bv = *(const float4*)(W + (size_t)(n0 + lrow) * K + ka);
        As[lk4+0][lrow] = av.x; As[lk4+1][lrow] = av.y;
        As[lk4+2][lrow] = av.z; As[lk4+3][lrow] = av.w;
        Bs[lk4+0][lrow] = bv.x; Bs[lk4+1][lrow] = bv.y;
        Bs[lk4+2][lrow] = bv.z; Bs[lk4+3][lrow] = bv.w;
        __syncthreads();

        #pragma unroll
        for (int kk = 0; kk < 8; kk++) {
            float a[8], b[8];
            #pragma unroll
            for (int i = 0; i < 8; i++) a[i] = As[kk][ty*8 + i];
            #pragma unroll
            for (int j = 0; j < 8; j++) b[j] = Bs[kk][tx*8 + j];
            #pragma unroll
            for (int i = 0; i < 8; i++)
                #pragma unroll
                for (int j = 0; j < 8; j++)
                    acc[i][j] += a[i] * b[j];
        }
        __syncthreads();
    }

    #pragma unroll
    for (int j = 0; j < 8; j++) {
        const int n   = n0 + tx*8 + j;
        const int dir = n >> 9;
        const int jj  = n & 511;
        const float bsum = bias[dir*1024 + jj] + bias[dir*1024 + 512 + jj];
        #pragma unroll
        for (int i = 0; i < 8; i++) {
            const int m = m0 + ty*8 + i;
            out[(size_t)dir * DIR_STRIDE + (size_t)m * 512 + jj] = acc[i][j] + bsum;
        }
    }
}

// ---------------------------------------------------------------------------
// Persistent recurrence kernel v2: 128 CTAs (64/dir), 128 threads (4 warps).
// k-chunk decomposition: warp w covers k in [128w, 128w+128); lane = batch b.
// Each warp computes partial sums for ALL 8 j-columns of this CTA over its
// k-chunk (h read from L2 exactly once per CTA per step), then a cross-warp
// smem reduction finalizes. Sync: release-atomic arrival counter + broadcast
// epoch flag polled with acquire loads. No __threadfence anywhere.
// ---------------------------------------------------------------------------
template<int LAYER>
__global__ __launch_bounds__(128) void rec_kernel(
    const float* __restrict__ pre, const float* __restrict__ Whh,
    float* __restrict__ outA, float* __restrict__ hy)
{
    __shared__ float4 Wsh4[8 * 128];    // W rows [j0, j0+8), [j][k4]
    __shared__ float  Red[4 * 8 * 32];  // partials [warp][j][b]

    const int dir = blockIdx.x >> 6;
    const int j0  = (blockIdx.x & 63) * 8;
    const int tid = threadIdx.x;
    const int w   = tid >> 5;          // warp id = k-chunk id = output j-pair id
    const int b   = tid & 31;          // batch lane
    const int ja  = 2*w, jb = 2*w + 1; // this thread's output columns (local)

    // Load W_hh rows [j0, j0+8) for this direction into smem (contiguous)
    const float4* Wb4 = (const float4*)(Whh + (size_t)dir * (HH*HH) + (size_t)j0 * HH);
    for (int i = tid; i < 8 * 128; i += 128) Wsh4[i] = Wb4[i];
    __syncthreads();

    int* cnt  = &g_cnt[LAYER][dir][0];
    int* flag = &g_flag[LAYER][dir][0];

    for (int t = 0; t < TT; t++) {
        const int tau = dir ? (TT - 1 - t) : t;
        const size_t pidx = (size_t)dir * DIR_STRIDE + (size_t)(tau*32 + b) * 512 + j0;
        float s0 = pre[pidx + ja];
        float s1 = pre[pidx + jb];

        if (t > 0) {
            // Wait for all 64 CTAs of this direction to finish step t-1.
            if (tid == 0) {
                while (ld_acquire_gpu(flag) < t) { }
            }
            __syncthreads();

            // Partial mat-vec over this warp's k-chunk, all 8 j's.
            float acc[8];
            #pragma unroll
            for (int j = 0; j < 8; j++) acc[j] = 0.0f;

            const float4* hp = (const float4*)&g_hbuf[dir][(t-1) & 1][0]
                               + (size_t)b * 128 + w * 32;
            const float4* wp = Wsh4 + w * 32;
            #pragma unroll 8
            for (int q = 0; q < 32; q++) {
                const float4 h4 = __ldcg(hp + q);
                #pragma unroll
                for (int j = 0; j < 8; j++) {
                    const float4 w4 = wp[j * 128 + q];
                    acc[j] += h4.x*w4.x + h4.y*w4.y + h4.z*w4.z + h4.w*w4.w;
                }
            }

            // Cross-warp reduce: Red[w][j][b]
            #pragma unroll
            for (int j = 0; j < 8; j++) Red[(w*8 + j)*32 + b] = acc[j];
            __syncthreads();

            #pragma unroll
            for (int ww = 0; ww < 4; ww++) {
                s0 += Red[(ww*8 + ja)*32 + b];
                s1 += Red[(ww*8 + jb)*32 + b];
            }
        }

        const float v0 = tanhf(s0);
        const float v1 = tanhf(s1);

        // Publish h for next step (plain stores; release-atomic orders them).
        float* hb = &g_hbuf[dir][t & 1][b * 512 + j0];
        hb[ja] = v0; hb[jb] = v1;

        // Layer outputs.
        if (LAYER == 0) {
            float* o = outA + pidx;            // same layout as pre
            o[ja] = v0; o[jb] = v1;
        } else {
            float* o = outA + (size_t)b * (TT*2*HH) + (size_t)tau * (2*HH) + dir * 512 + j0;
            o[ja] = v0; o[jb] = v1;
        }
        if (t == TT - 1) {
            float* o = hy + (size_t)(LAYER*2 + dir) * (BB*HH) + b * 512 + j0;
            o[ja] = v0; o[jb] = v1;
        } else {
            // Arrive: all threads' stores are CTA-ordered by bar.sync, then the
            // release-atomic makes them GPU-visible transitively.
            __syncthreads();
            if (tid == 0) {
                const int old = atom_add_release_gpu(cnt, 1);
                if (old == 64*(t+1) - 1) st_release_gpu(flag, t + 1);
            }
        }
    }
}

extern "C" void kernel_launch(void* const* d_in, const int* in_sizes, int n_in,
                              void* d_out, int out_size)
{
    const float* xs    = (const float*)d_in[0];
    const float* w_ih0 = (const float*)d_in[1];
    const float* w_hh0 = (const float*)d_in[2];
    const float* b0    = (const float*)d_in[3];
    const float* w_ih1 = (const float*)d_in[4];
    const float* w_hh1 = (const float*)d_in[5];
    const float* b1    = (const float*)d_in[6];

    float* out_hs = (float*)d_out;                       // [B][T][2H]
    float* out_hy = (float*)d_out + (size_t)BB*TT*2*HH;  // [4][B][H]

    float* pre; cudaGetSymbolAddress((void**)&pre, g_pre);
    float* seq; cudaGetSymbolAddress((void**)&seq, g_seq);

    zero_counters<<<1, 128>>>();

    // Layer 0 input projection: K=256
    gemm_kernel<0><<<dim3(8, 128), 256>>>(xs, w_ih0, b0, pre, EE);
    // Layer 0 recurrence (both directions concurrently)
    rec_kernel<0><<<128, 128>>>(pre, w_hh0, seq, out_hy);
    // Layer 1 input projection: K=1024 over concatenated directions
    gemm_kernel<1><<<dim3(8, 128), 256>>>(seq, w_ih1, b1, pre, 2*HH);
    // Layer 1 recurrence, writes final hs + hy
    rec_kernel<1><<<128, 128>>>(pre, w_hh1, out_hs, out_hy);
}

// round 5
// speedup vs baseline: 2.3867x; 1.0283x over previous
#include <cuda_runtime.h>
#include <cstdint>

// Problem constants
#define TT 512
#define BB 32
#define EE 256
#define HH 512
#define SEQ_ELEMS (2*TT*BB*HH)   // 16777216
#define DIR_STRIDE (TT*BB*HH)    // 8388608

// Scratch (static device memory; no allocations allowed)
__device__ float g_pre[SEQ_ELEMS];      // pre-activations (layout [dir][t*32+b][512])
__device__ float g_seq[SEQ_ELEMS];      // layer-0 hidden sequence, same layout
// h double buffer, TRANSPOSED-INTERLEAVED: [dir][buf][ (k>>2)*128 + b*4 + (k&3) ]
__device__ float g_hbuf[2][2][BB*HH];
// One flag line per CTA: [layer][dir][cta][pad]
__device__ __align__(128) int g_flagA[2][2][64][32];

__global__ void zero_flags() {
    int i = threadIdx.x;
    if (i < 256) g_flagA[i >> 7][(i >> 6) & 1][i & 63][0] = 0;
}

// ---- f32x2 + scoped memory helpers ----------------------------------------
__device__ __forceinline__ unsigned long long ffma2(
    unsigned long long a, unsigned long long b, unsigned long long c) {
    unsigned long long d;
    asm("fma.rn.f32x2 %0, %1, %2, %3;" : "=l"(d) : "l"(a), "l"(b), "l"(c));
    return d;
}
__device__ __forceinline__ unsigned long long pack2(float lo, float hi) {
    unsigned long long v;
    asm("mov.b64 %0, {%1, %2};" : "=l"(v) : "f"(lo), "f"(hi));
    return v;
}
__device__ __forceinline__ void unpack2(unsigned long long v, float& lo, float& hi) {
    asm("mov.b64 {%0, %1}, %2;" : "=f"(lo), "=f"(hi) : "l"(v));
}
__device__ __forceinline__ int ld_acquire_gpu(const int* p) {
    int v;
    asm volatile("ld.acquire.gpu.global.s32 %0, [%1];" : "=r"(v) : "l"(p));
    return v;
}
__device__ __forceinline__ void st_release_gpu(int* p, int v) {
    asm volatile("st.release.gpu.global.s32 [%0], %1;" :: "l"(p), "r"(v));
}

// ---------------------------------------------------------------------------
// SGEMM-NT with f32x2 inner: out[m][n] = sum_k A[m][k]*W[n][k] + bias(n)
// ---------------------------------------------------------------------------
template<int MODE>
__global__ __launch_bounds__(256) void gemm_kernel(
    const float* __restrict__ A, const float* __restrict__ W,
    const float* __restrict__ bias, float* __restrict__ out, int K)
{
    __shared__ float As[8][128];
    __shared__ float Bs[8][128];
    const int tid = threadIdx.x;
    const int m0 = blockIdx.y * 128;
    const int n0 = blockIdx.x * 128;
    const int lrow = tid >> 1;
    const int lk4  = (tid & 1) * 4;
    const int tx = tid & 15, ty = tid >> 4;

    unsigned long long acc2[8][4];
    #pragma unroll
    for (int i = 0; i < 8; i++)
        #pragma unroll
        for (int jp = 0; jp < 4; jp++) acc2[i][jp] = 0ull;

    for (int k0 = 0; k0 < K; k0 += 8) {
        const int ka = k0 + lk4;
        const int m  = m0 + lrow;
        float4 av;
        if (MODE == 0) {
            av = *(const float4*)(A + (size_t)(m & 31) * (TT*EE) + (size_t)(m >> 5) * EE + ka);
        } else {
            av = *(const float4*)(A + (size_t)(ka >> 9) * DIR_STRIDE + (size_t)m * 512 + (ka & 511));
        }
        float4 bv = *(const float4*)(W + (size_t)(n0 + lrow) * K + ka);
        As[lk4+0][lrow] = av.x; As[lk4+1][lrow] = av.y;
        As[lk4+2][lrow] = av.z; As[lk4+3][lrow] = av.w;
        Bs[lk4+0][lrow] = bv.x; Bs[lk4+1][lrow] = bv.y;
        Bs[lk4+2][lrow] = bv.z; Bs[lk4+3][lrow] = bv.w;
        __syncthreads();

        #pragma unroll
        for (int kk = 0; kk < 8; kk++) {
            unsigned long long ap[8], b2[4];
            #pragma unroll
            for (int i = 0; i < 8; i++) {
                const float a = As[kk][ty*8 + i];
                ap[i] = pack2(a, a);
            }
            const unsigned long long* bp =
                (const unsigned long long*)&Bs[kk][tx*8];
            #pragma unroll
            for (int jp = 0; jp < 4; jp++) b2[jp] = bp[jp];
            #pragma unroll
            for (int i = 0; i < 8; i++)
                #pragma unroll
                for (int jp = 0; jp < 4; jp++)
                    acc2[i][jp] = ffma2(ap[i], b2[jp], acc2[i][jp]);
        }
        __syncthreads();
    }

    #pragma unroll
    for (int jp = 0; jp < 4; jp++) {
        #pragma unroll
        for (int h = 0; h < 2; h++) {
            const int n   = n0 + tx*8 + jp*2 + h;
            const int dir = n >> 9;
            const int jj  = n & 511;
            const float bsum = bias[dir*1024 + jj] + bias[dir*1024 + 512 + jj];
            #pragma unroll
            for (int i = 0; i < 8; i++) {
                float lo, hi; unpack2(acc2[i][jp], lo, hi);
                const float val = h ? hi : lo;
                const int m = m0 + ty*8 + i;
                out[(size_t)dir * DIR_STRIDE + (size_t)m * 512 + jj] = val + bsum;
            }
        }
    }
}

// ---------------------------------------------------------------------------
// Persistent recurrence kernel v3: 128 CTAs (64/dir), 128 threads (4 warps).
//  - h stored transposed-interleaved -> coalesced LDG.128 (4 wf each)
//  - warp w covers k-chunk [128w,128w+128) for all 8 j cols; smem reduce
//  - f32x2 FMA (512 FFMA2/thread/step)
//  - pre staged coalesced through smem; outputs written cooperatively
//    AFTER the flag release (off the inter-CTA critical path)
//  - per-CTA release flags polled by 64 threads in parallel
// ---------------------------------------------------------------------------
template<int LAYER>
__global__ __launch_bounds__(128) void rec_kernel(
    const float* __restrict__ pre, const float* __restrict__ Whh,
    float* __restrict__ outA, float* __restrict__ hy)
{
    __shared__ float4 Wsh4[8 * 128];    // W rows [j0, j0+8): [j][k4]
    __shared__ float  Red[4 * 8 * 32];  // partials [warp][j][b]
    __shared__ float  PreS[8 * 32];     // staged pre [jl][b]
    __shared__ float  Vsm[8 * 32];      // outputs   [jl][b]

    const int dir = blockIdx.x >> 6;
    const int cta = blockIdx.x & 63;
    const int j0  = cta * 8;
    const int tid = threadIdx.x;
    const int w   = tid >> 5;          // warp id = k-chunk id
    const int b   = tid & 31;          // batch lane
    const int ja  = 2*w, jb = 2*w + 1; // this thread's output columns (local)
    const int pr  = tid >> 2, pc = tid & 3;  // coalesced pre/seq tile mapping

    // Load W_hh rows [j0, j0+8) into smem (contiguous)
    const float4* Wb4 = (const float4*)(Whh + (size_t)dir * (HH*HH) + (size_t)j0 * HH);
    for (int i = tid; i < 8 * 128; i += 128) Wsh4[i] = Wb4[i];
    __syncthreads();

    const float* preDir = pre + (size_t)dir * DIR_STRIDE;
    int* myflag = &g_flagA[LAYER][dir][cta][0];
    const int* flags = &g_flagA[LAYER][dir][0][0];

    for (int t = 0; t < TT; t++) {
        const int tau = dir ? (TT - 1 - t) : t;

        // Prefetch this step's pre tile (coalesced LDG.64, 8 wf/warp),
        // issued before the spin-wait so latency hides under it.
        const float2 pv = *(const float2*)(preDir
                            + (size_t)(tau*32 + pr) * 512 + j0 + pc*2);
        PreS[(pc*2)   * 32 + pr] = pv.x;
        PreS[(pc*2+1) * 32 + pr] = pv.y;

        if (t > 0) {
            // Wait for all 64 CTAs of this dir: 64 threads poll 64 flags.
            if (tid < 64) {
                while (ld_acquire_gpu(flags + tid*32) < t) { }
            }
            __syncthreads();   // bar A

            // Partial mat-vec over this warp's k-chunk, all 8 j's (f32x2).
            unsigned long long acc2[8];
            #pragma unroll
            for (int j = 0; j < 8; j++) acc2[j] = 0ull;

            const float4* hv = (const float4*)&g_hbuf[dir][(t-1) & 1][0];
            const ulonglong2* wp = (const ulonglong2*)Wsh4 + w*32;
            #pragma unroll 4
            for (int q = 0; q < 32; q++) {
                // coalesced: lanes read consecutive float4s (512B/warp)
                const float4 h4 = __ldcg(hv + (w*32 + q)*32 + b);
                const unsigned long long h01 = pack2(h4.x, h4.y);
                const unsigned long long h23 = pack2(h4.z, h4.w);
                #pragma unroll
                for (int j = 0; j < 8; j++) {
                    const ulonglong2 w2 = wp[j*128 + q];   // broadcast LDS.128
                    acc2[j] = ffma2(h01, w2.x, acc2[j]);
                    acc2[j] = ffma2(h23, w2.y, acc2[j]);
                }
            }
            #pragma unroll
            for (int j = 0; j < 8; j++) {
                float lo, hi; unpack2(acc2[j], lo, hi);
                Red[(w*8 + j)*32 + b] = lo + hi;
            }
        }
        __syncthreads();       // bar B (also publishes PreS at t==0)

        float s0 = PreS[ja*32 + b];
        float s1 = PreS[jb*32 + b];
        if (t > 0) {
            #pragma unroll
            for (int ww = 0; ww < 4; ww++) {
                s0 += Red[(ww*8 + ja)*32 + b];
                s1 += Red[(ww*8 + jb)*32 + b];
            }
        }
        const float v0 = tanhf(s0);
        const float v1 = tanhf(s1);

        // Publish h in transposed-interleaved layout (float2, ~4 lines/warp).
        {
            const int g = (j0 + 2*w) >> 2;
            *(float2*)&g_hbuf[dir][t & 1][g*128 + b*4 + ((2*w) & 3)]
                = make_float2(v0, v1);
        }
        Vsm[ja*32 + b] = v0;
        Vsm[jb*32 + b] = v1;

        if (t == TT - 1) {
            float* o = hy + (size_t)(LAYER*2 + dir) * (BB*HH) + b*512 + j0;
            o[ja] = v0; o[jb] = v1;
        }

        __syncthreads();       // bar C: hbuf + Vsm stores visible CTA-wide
        if (t < TT - 1 && tid == 0) st_release_gpu(myflag, t + 1);

        // Cooperative layer-output store from Vsm — AFTER the flag release,
        // so it overlaps other CTAs' progress (only gemm/stream order needs it).
        if (LAYER == 0) {
            const float2 ov = make_float2(Vsm[(pc*2)*32 + pr],
                                          Vsm[(pc*2+1)*32 + pr]);
            *(float2*)(outA + (size_t)dir * DIR_STRIDE
                       + (size_t)(tau*32 + pr)*512 + j0 + pc*2) = ov;
        } else {
            if (tid < 32) {
                const float4 o1 = make_float4(Vsm[0*32+tid], Vsm[1*32+tid],
                                              Vsm[2*32+tid], Vsm[3*32+tid]);
                const float4 o2 = make_float4(Vsm[4*32+tid], Vsm[5*32+tid],
                                              Vsm[6*32+tid], Vsm[7*32+tid]);
                float* o = outA + (size_t)tid * (TT*2*HH)
                           + (size_t)tau * (2*HH) + dir*512 + j0;
                *(float4*)o = o1;
                *((float4*)o + 1) = o2;
            }
        }
    }
}

extern "C" void kernel_launch(void* const* d_in, const int* in_sizes, int n_in,
                              void* d_out, int out_size)
{
    const float* xs    = (const float*)d_in[0];
    const float* w_ih0 = (const float*)d_in[1];
    const float* w_hh0 = (const float*)d_in[2];
    const float* b0    = (const float*)d_in[3];
    const float* w_ih1 = (const float*)d_in[4];
    const float* w_hh1 = (const float*)d_in[5];
    const float* b1    = (const float*)d_in[6];

    float* out_hs = (float*)d_out;                       // [B][T][2H]
    float* out_hy = (float*)d_out + (size_t)BB*TT*2*HH;  // [4][B][H]

    float* pre; cudaGetSymbolAddress((void**)&pre, g_pre);
    float* seq; cudaGetSymbolAddress((void**)&seq, g_seq);

    zero_flags<<<1, 256>>>();

    // Layer 0 input projection: K=256
    gemm_kernel<0><<<dim3(8, 128), 256>>>(xs, w_ih0, b0, pre, EE);
    // Layer 0 recurrence (both directions concurrently)
    rec_kernel<0><<<128, 128>>>(pre, w_hh0, seq, out_hy);
    // Layer 1 input projection: K=1024 over concatenated directions
    gemm_kernel<1><<<dim3(8, 128), 256>>>(seq, w_ih1, b1, pre, 2*HH);
    // Layer 1 recurrence, writes final hs + hy
    rec_kernel<1><<<128, 128>>>(pre, w_hh1, out_hs, out_hy);
}